// round 2
// baseline (speedup 1.0000x reference)
#include <cuda_runtime.h>
#include <math.h>

// ---------------------------------------------------------------------------
// LNN_16234976379185 — algebraically collapsed leaky-integrator MLP.
//
//   d1  = relu(x @ W1^T + b1)                (time-invariant)
//   y   = d1 @ W2^T                          (time-invariant)
//   s2 recurrence is elementwise on y        (T steps, cheap)
//   out = (sum_t w_t s2_t) @ W3^T + (1-b3^T) b3
//
// Three GEMMs + one elementwise pass instead of 30 GEMMs.
// ---------------------------------------------------------------------------

#define BM 128
#define BN 128
#define BK 8
#define TM 8
#define TN 8

static const int MAX_B = 1024;
static const int MAX_H = 4096;

__device__ float g_d1[MAX_B * MAX_H];
__device__ float g_y[MAX_B * MAX_H];
__device__ float g_s2acc[MAX_B * MAX_H];

__device__ __forceinline__ float sigmoid_acc(float v) {
    return 1.0f / (1.0f + expf(-v));
}

// C[M,N] = A[M,K] @ B[N,K]^T   (both operands K-contiguous: "NT" gemm)
// mode 0: C = relu(AB^T + bias)
// mode 1: C = AB^T
// mode 2: C = AB^T + (1 - beta3^T) * bias
__global__ void __launch_bounds__(256, 2)
gemm_nt(const float* __restrict__ A, const float* __restrict__ Bm,
        const float* __restrict__ bias, float* __restrict__ C,
        int M, int N, int K, int mode,
        const float* __restrict__ b_taus, const int* __restrict__ Tp)
{
    __shared__ float As[BK][BM];
    __shared__ float Bs[BK][BN];

    const int tid  = threadIdx.x;
    const int tx   = tid & 15;          // 0..15  (N direction)
    const int ty   = tid >> 4;          // 0..15  (M direction)
    const int lrow = tid >> 1;          // 0..127 (row loaded by this thread)
    const int lcol = (tid & 1) << 2;    // 0 or 4 (k offset, float4)

    const float* Ag = A  + (size_t)(blockIdx.y * BM + lrow) * K + lcol;
    const float* Bg = Bm + (size_t)(blockIdx.x * BN + lrow) * K + lcol;

    float acc[TM][TN];
#pragma unroll
    for (int i = 0; i < TM; i++)
#pragma unroll
        for (int j = 0; j < TN; j++) acc[i][j] = 0.0f;

    for (int k0 = 0; k0 < K; k0 += BK) {
        float4 a4 = *(const float4*)(Ag + k0);
        float4 b4 = *(const float4*)(Bg + k0);
        As[lcol + 0][lrow] = a4.x;
        As[lcol + 1][lrow] = a4.y;
        As[lcol + 2][lrow] = a4.z;
        As[lcol + 3][lrow] = a4.w;
        Bs[lcol + 0][lrow] = b4.x;
        Bs[lcol + 1][lrow] = b4.y;
        Bs[lcol + 2][lrow] = b4.z;
        Bs[lcol + 3][lrow] = b4.w;
        __syncthreads();

#pragma unroll
        for (int k = 0; k < BK; k++) {
            float4 a0 = *(const float4*)&As[k][ty * TM];
            float4 a1 = *(const float4*)&As[k][ty * TM + 4];
            float4 b0 = *(const float4*)&Bs[k][tx * TN];
            float4 b1 = *(const float4*)&Bs[k][tx * TN + 4];
            float ar[TM] = {a0.x, a0.y, a0.z, a0.w, a1.x, a1.y, a1.z, a1.w};
            float br[TN] = {b0.x, b0.y, b0.z, b0.w, b1.x, b1.y, b1.z, b1.w};
#pragma unroll
            for (int m = 0; m < TM; m++)
#pragma unroll
                for (int n = 0; n < TN; n++)
                    acc[m][n] = fmaf(ar[m], br[n], acc[m][n]);
        }
        __syncthreads();
    }

    float bscale = 0.0f;
    if (mode == 2) {
        float beta3 = sigmoid_acc(b_taus[2]);
        int   T     = *Tp;
        bscale = 1.0f - powf(beta3, (float)T);
    }

    const int row0 = blockIdx.y * BM + ty * TM;
    const int col0 = blockIdx.x * BN + tx * TN;
#pragma unroll
    for (int m = 0; m < TM; m++) {
        float* Cp = C + (size_t)(row0 + m) * N + col0;
#pragma unroll
        for (int n = 0; n < TN; n++) {
            float v = acc[m][n];
            if (mode == 0)       v = fmaxf(v + bias[col0 + n], 0.0f);
            else if (mode == 2)  v = v + bscale * bias[col0 + n];
            Cp[n] = v;
        }
    }
}

// For each element of y [B, H2]:
//   s2 = 0; acc = 0; bp = beta1 (beta1^t); wt = (1-b3)*b3^(T-1)
//   for t = 1..T:
//     d2  = relu((1 - bp) * y + b2[col])
//     s2  = b2g * s2 + (1 - b2g) * d2
//     acc += wt * s2
//     bp *= beta1; wt /= beta3
__global__ void __launch_bounds__(256)
lnn_scan_elem(const float* __restrict__ y, const float* __restrict__ b2,
              float* __restrict__ out, int total, int H,
              const float* __restrict__ b_taus, const int* __restrict__ Tp)
{
    int i    = blockIdx.x * blockDim.x + threadIdx.x;
    int idx4 = i * 4;
    if (idx4 >= total) return;

    float beta1 = sigmoid_acc(b_taus[0]);
    float beta2 = sigmoid_acc(b_taus[1]);
    float beta3 = sigmoid_acc(b_taus[2]);
    int   T     = *Tp;

    float4 yv = *(const float4*)(y + idx4);
    int    j  = idx4 % H;                       // H multiple of 4
    float4 bb = *(const float4*)(b2 + j);

    float  bp    = beta1;
    float  wt    = (1.0f - beta3) * powf(beta3, (float)(T - 1));
    float  invb3 = 1.0f / beta3;
    float  om2   = 1.0f - beta2;

    float4 s2 = make_float4(0.f, 0.f, 0.f, 0.f);
    float4 ac = make_float4(0.f, 0.f, 0.f, 0.f);

    for (int t = 0; t < T; t++) {
        float c = 1.0f - bp;
        float d;
        d = fmaxf(fmaf(c, yv.x, bb.x), 0.0f); s2.x = fmaf(beta2, s2.x, om2 * d); ac.x = fmaf(wt, s2.x, ac.x);
        d = fmaxf(fmaf(c, yv.y, bb.y), 0.0f); s2.y = fmaf(beta2, s2.y, om2 * d); ac.y = fmaf(wt, s2.y, ac.y);
        d = fmaxf(fmaf(c, yv.z, bb.z), 0.0f); s2.z = fmaf(beta2, s2.z, om2 * d); ac.z = fmaf(wt, s2.z, ac.z);
        d = fmaxf(fmaf(c, yv.w, bb.w), 0.0f); s2.w = fmaf(beta2, s2.w, om2 * d); ac.w = fmaf(wt, s2.w, ac.w);
        bp *= beta1;
        wt *= invb3;
    }
    *(float4*)(out + idx4) = ac;
}

extern "C" void kernel_launch(void* const* d_in, const int* in_sizes, int n_in,
                              void* d_out, int out_size)
{
    const float* x     = (const float*)d_in[0];
    const float* W1    = (const float*)d_in[1];
    const float* b1    = (const float*)d_in[2];
    const float* W2    = (const float*)d_in[3];
    const float* b2    = (const float*)d_in[4];
    const float* W3    = (const float*)d_in[5];
    const float* b3    = (const float*)d_in[6];
    const float* btaus = (const float*)d_in[7];
    const int*   Tp    = (const int*)d_in[8];

    const int H1    = in_sizes[2];
    const int D_IN  = in_sizes[1] / H1;
    const int B     = in_sizes[0] / D_IN;
    const int H2    = in_sizes[4];
    const int D_OUT = in_sizes[6];

    float *d1, *y, *s2acc;
    cudaGetSymbolAddress((void**)&d1,    g_d1);
    cudaGetSymbolAddress((void**)&y,     g_y);
    cudaGetSymbolAddress((void**)&s2acc, g_s2acc);

    float* out = (float*)d_out;

    // 1) d1 = relu(x @ W1^T + b1)        [B, H1]
    {
        dim3 grid(H1 / BN, B / BM);
        gemm_nt<<<grid, 256>>>(x, W1, b1, d1, B, H1, D_IN, 0, btaus, Tp);
    }
    // 2) y = d1 @ W2^T                   [B, H2]
    {
        dim3 grid(H2 / BN, B / BM);
        gemm_nt<<<grid, 256>>>(d1, W2, nullptr, y, B, H2, H1, 1, btaus, Tp);
    }
    // 3) elementwise T-step scan -> s2acc = sum_t w_t s2_t   [B, H2]
    {
        int total  = B * H2;
        int threads = 256;
        int blocks  = (total / 4 + threads - 1) / threads;
        lnn_scan_elem<<<blocks, threads>>>(y, b2, s2acc, total, H2, btaus, Tp);
    }
    // 4) out = s2acc @ W3^T + (1 - beta3^T) * b3   [B, D_OUT]
    {
        dim3 grid(D_OUT / BN, B / BM);
        gemm_nt<<<grid, 256>>>(s2acc, W3, b3, out, B, D_OUT, H2, 2, btaus, Tp);
    }
    (void)n_in; (void)out_size;
}

// round 3
// speedup vs baseline: 1.2807x; 1.2807x over previous
#include <cuda_runtime.h>
#include <math.h>

// ---------------------------------------------------------------------------
// LNN_16234976379185 — collapsed leaky-integrator MLP, f32x2-packed SGEMM.
//
//   d1    = relu(x @ W1^T + b1)              (GEMM1, mode RELU)
//   s2acc = scan-epilogue(d1 @ W2^T)         (GEMM2, mode SCAN — y never stored)
//   part  = split-K slabs of s2acc @ W3^T    (GEMM3, mode PART, 4-way split-K)
//   out   = (1-b3^T) b3 + sum(part)          (reduce)
// ---------------------------------------------------------------------------

#define BM 128
#define BN 128
#define BK 8
#define TM 8
#define TN 8
#define KSPLIT 4

#define MODE_RELU 0
#define MODE_SCAN 1
#define MODE_PART 2

static const int MAX_B = 1024;
static const int MAX_H = 4096;

typedef unsigned long long u64;

__device__ float g_d1[MAX_B * MAX_H];
__device__ float g_part[MAX_B * MAX_H];   // reused: KSPLIT * B * D_OUT = 4M floats
__device__ float g_s2acc[MAX_B * MAX_H];

__device__ __forceinline__ float sigmoid_acc(float v) {
    return 1.0f / (1.0f + expf(-v));
}

__device__ __forceinline__ u64 splat2(float a) {
    u64 r; asm("mov.b64 %0, {%1, %1};" : "=l"(r) : "f"(a)); return r;
}
__device__ __forceinline__ void ffma2(u64& d, u64 a, u64 b) {
    asm("fma.rn.f32x2 %0, %1, %2, %3;" : "=l"(d) : "l"(a), "l"(b), "l"(d));
}
__device__ __forceinline__ float2 unpack2(u64 v) {
    float2 f; asm("mov.b64 {%0, %1}, %2;" : "=f"(f.x), "=f"(f.y) : "l"(v)); return f;
}

// C[M,N] = A[M,K] @ B[N,K]^T   (both K-contiguous). Packed-f32x2 inner product.
__global__ void __launch_bounds__(256, 2)
gemm_nt2(const float* __restrict__ A, const float* __restrict__ Bm,
         const float* __restrict__ bias, float* __restrict__ C,
         int M, int N, int K, int mode,
         const float* __restrict__ b_taus, const int* __restrict__ Tp)
{
    __shared__ float As[2][BK][BM];
    __shared__ float Bs[2][BK][BN];

    const int tid  = threadIdx.x;
    const int tx   = tid & 15;          // N direction (0..15)
    const int ty   = tid >> 4;          // M direction (0..15)
    const int lrow = tid >> 1;          // row this thread loads (0..127)
    const int lcol = (tid & 1) << 2;    // k offset (0 or 4)

    // split-K slab (z dimension); K passed is the slab length
    const int kbase = blockIdx.z * K;

    const float* Ag = A  + (size_t)(blockIdx.y * BM + lrow) * ((size_t)K * gridDim.z) + kbase + lcol;
    const float* Bg = Bm + (size_t)(blockIdx.x * BN + lrow) * ((size_t)K * gridDim.z) + kbase + lcol;

    u64 acc2[TM][TN / 2];
#pragma unroll
    for (int m = 0; m < TM; m++)
#pragma unroll
        for (int n = 0; n < TN / 2; n++) acc2[m][n] = 0ull;

    // prologue: fill buffer 0
    {
        float4 a4 = *(const float4*)(Ag);
        float4 b4 = *(const float4*)(Bg);
        As[0][lcol + 0][lrow] = a4.x; As[0][lcol + 1][lrow] = a4.y;
        As[0][lcol + 2][lrow] = a4.z; As[0][lcol + 3][lrow] = a4.w;
        Bs[0][lcol + 0][lrow] = b4.x; Bs[0][lcol + 1][lrow] = b4.y;
        Bs[0][lcol + 2][lrow] = b4.z; Bs[0][lcol + 3][lrow] = b4.w;
    }
    __syncthreads();

    int buf = 0;
    for (int k0 = 0; k0 < K; k0 += BK) {
        float4 a4n, b4n;
        const bool more = (k0 + BK) < K;
        if (more) {
            a4n = *(const float4*)(Ag + k0 + BK);
            b4n = *(const float4*)(Bg + k0 + BK);
        }

#pragma unroll
        for (int k = 0; k < BK; k++) {
            float4 a0 = *(const float4*)&As[buf][k][ty * TM];
            float4 a1 = *(const float4*)&As[buf][k][ty * TM + 4];
            ulonglong2 bp0 = *(const ulonglong2*)&Bs[buf][k][tx * TN];
            ulonglong2 bp1 = *(const ulonglong2*)&Bs[buf][k][tx * TN + 4];
            u64 br[4] = {bp0.x, bp0.y, bp1.x, bp1.y};
            float ar[TM] = {a0.x, a0.y, a0.z, a0.w, a1.x, a1.y, a1.z, a1.w};
#pragma unroll
            for (int m = 0; m < TM; m++) {
                u64 am2 = splat2(ar[m]);
#pragma unroll
                for (int n = 0; n < TN / 2; n++)
                    ffma2(acc2[m][n], am2, br[n]);
            }
        }

        if (more) {
            int nb = buf ^ 1;
            As[nb][lcol + 0][lrow] = a4n.x; As[nb][lcol + 1][lrow] = a4n.y;
            As[nb][lcol + 2][lrow] = a4n.z; As[nb][lcol + 3][lrow] = a4n.w;
            Bs[nb][lcol + 0][lrow] = b4n.x; Bs[nb][lcol + 1][lrow] = b4n.y;
            Bs[nb][lcol + 2][lrow] = b4n.z; Bs[nb][lcol + 3][lrow] = b4n.w;
            buf = nb;
            __syncthreads();
        }
    }

    const int row0 = blockIdx.y * BM + ty * TM;
    const int col0 = blockIdx.x * BN + tx * TN;

    if (mode == MODE_RELU) {
        float4 bb0 = *(const float4*)(bias + col0);
        float4 bb1 = *(const float4*)(bias + col0 + 4);
        float bv[8] = {bb0.x, bb0.y, bb0.z, bb0.w, bb1.x, bb1.y, bb1.z, bb1.w};
#pragma unroll
        for (int m = 0; m < TM; m++) {
            float* Cp = C + (size_t)(row0 + m) * N + col0;
            float4 o0, o1;
            float2 p0 = unpack2(acc2[m][0]), p1 = unpack2(acc2[m][1]);
            float2 p2 = unpack2(acc2[m][2]), p3 = unpack2(acc2[m][3]);
            o0.x = fmaxf(p0.x + bv[0], 0.f); o0.y = fmaxf(p0.y + bv[1], 0.f);
            o0.z = fmaxf(p1.x + bv[2], 0.f); o0.w = fmaxf(p1.y + bv[3], 0.f);
            o1.x = fmaxf(p2.x + bv[4], 0.f); o1.y = fmaxf(p2.y + bv[5], 0.f);
            o1.z = fmaxf(p3.x + bv[6], 0.f); o1.w = fmaxf(p3.y + bv[7], 0.f);
            *(float4*)(Cp)     = o0;
            *(float4*)(Cp + 4) = o1;
        }
    } else if (mode == MODE_SCAN) {
        // y = acc; run T-step s1/s2 recurrence per element, emit sum_t w_t s2_t
        float beta1 = sigmoid_acc(b_taus[0]);
        float beta2 = sigmoid_acc(b_taus[1]);
        float beta3 = sigmoid_acc(b_taus[2]);
        int   T     = *Tp;
        float invb3 = 1.0f / beta3;
        float om2   = 1.0f - beta2;
        float wt0   = (1.0f - beta3) * powf(beta3, (float)(T - 1));

        float4 bb0 = *(const float4*)(bias + col0);
        float4 bb1 = *(const float4*)(bias + col0 + 4);
        float bv[8] = {bb0.x, bb0.y, bb0.z, bb0.w, bb1.x, bb1.y, bb1.z, bb1.w};

#pragma unroll
        for (int m = 0; m < TM; m++) {
            float yv[8];
            float2 p0 = unpack2(acc2[m][0]), p1 = unpack2(acc2[m][1]);
            float2 p2 = unpack2(acc2[m][2]), p3 = unpack2(acc2[m][3]);
            yv[0] = p0.x; yv[1] = p0.y; yv[2] = p1.x; yv[3] = p1.y;
            yv[4] = p2.x; yv[5] = p2.y; yv[6] = p3.x; yv[7] = p3.y;

            float s2[8], ac[8];
#pragma unroll
            for (int n = 0; n < 8; n++) { s2[n] = 0.f; ac[n] = 0.f; }
            float bp = beta1, wt = wt0;
            for (int t = 0; t < T; t++) {
                float c = 1.0f - bp;
#pragma unroll
                for (int n = 0; n < 8; n++) {
                    float d = fmaxf(fmaf(c, yv[n], bv[n]), 0.0f);
                    s2[n] = fmaf(beta2, s2[n], om2 * d);
                    ac[n] = fmaf(wt, s2[n], ac[n]);
                }
                bp *= beta1;
                wt *= invb3;
            }
            float* Cp = C + (size_t)(row0 + m) * N + col0;
            *(float4*)(Cp)     = make_float4(ac[0], ac[1], ac[2], ac[3]);
            *(float4*)(Cp + 4) = make_float4(ac[4], ac[5], ac[6], ac[7]);
        }
    } else { // MODE_PART: raw partial product into slab z
        float* Cz = C + (size_t)blockIdx.z * M * N;
#pragma unroll
        for (int m = 0; m < TM; m++) {
            float* Cp = Cz + (size_t)(row0 + m) * N + col0;
            float2 p0 = unpack2(acc2[m][0]), p1 = unpack2(acc2[m][1]);
            float2 p2 = unpack2(acc2[m][2]), p3 = unpack2(acc2[m][3]);
            *(float4*)(Cp)     = make_float4(p0.x, p0.y, p1.x, p1.y);
            *(float4*)(Cp + 4) = make_float4(p2.x, p2.y, p3.x, p3.y);
        }
    }
}

// out[i] = (1 - beta3^T) * b3[i % N] + sum_z part[z][i]
__global__ void __launch_bounds__(256)
reduce_out(const float* __restrict__ part, const float* __restrict__ b3,
           float* __restrict__ out, int total, int N,
           const float* __restrict__ b_taus, const int* __restrict__ Tp)
{
    int i = (blockIdx.x * blockDim.x + threadIdx.x) * 4;
    if (i >= total) return;
    float beta3 = sigmoid_acc(b_taus[2]);
    float bscale = 1.0f - powf(beta3, (float)(*Tp));

    int j = i % N;
    float4 bb = *(const float4*)(b3 + j);
    float4 s  = make_float4(bscale * bb.x, bscale * bb.y, bscale * bb.z, bscale * bb.w);
#pragma unroll
    for (int z = 0; z < KSPLIT; z++) {
        float4 p = *(const float4*)(part + (size_t)z * total + i);
        s.x += p.x; s.y += p.y; s.z += p.z; s.w += p.w;
    }
    *(float4*)(out + i) = s;
}

extern "C" void kernel_launch(void* const* d_in, const int* in_sizes, int n_in,
                              void* d_out, int out_size)
{
    const float* x     = (const float*)d_in[0];
    const float* W1    = (const float*)d_in[1];
    const float* b1    = (const float*)d_in[2];
    const float* W2    = (const float*)d_in[3];
    const float* b2    = (const float*)d_in[4];
    const float* W3    = (const float*)d_in[5];
    const float* b3    = (const float*)d_in[6];
    const float* btaus = (const float*)d_in[7];
    const int*   Tp    = (const int*)d_in[8];

    const int H1    = in_sizes[2];
    const int D_IN  = in_sizes[1] / H1;
    const int B     = in_sizes[0] / D_IN;
    const int H2    = in_sizes[4];
    const int D_OUT = in_sizes[6];

    float *d1, *part, *s2acc;
    cudaGetSymbolAddress((void**)&d1,    g_d1);
    cudaGetSymbolAddress((void**)&part,  g_part);
    cudaGetSymbolAddress((void**)&s2acc, g_s2acc);

    float* out = (float*)d_out;

    // 1) d1 = relu(x @ W1^T + b1)                       [B, H1]
    {
        dim3 grid(H1 / BN, B / BM, 1);
        gemm_nt2<<<grid, 256>>>(x, W1, b1, d1, B, H1, D_IN, MODE_RELU, btaus, Tp);
    }
    // 2) s2acc = scan-epilogue(d1 @ W2^T) with b2        [B, H2]
    {
        dim3 grid(H2 / BN, B / BM, 1);
        gemm_nt2<<<grid, 256>>>(d1, W2, b2, s2acc, B, H2, H1, MODE_SCAN, btaus, Tp);
    }
    // 3) split-K partials of s2acc @ W3^T                [KSPLIT][B, D_OUT]
    {
        dim3 grid(D_OUT / BN, B / BM, KSPLIT);
        gemm_nt2<<<grid, 256>>>(s2acc, W3, nullptr, part, B, D_OUT, H2 / KSPLIT,
                                MODE_PART, btaus, Tp);
    }
    // 4) out = (1-b3^T) b3 + sum partials                [B, D_OUT]
    {
        int total = B * D_OUT;
        reduce_out<<<(total / 4 + 255) / 256, 256>>>(part, b3, out, total, D_OUT, btaus, Tp);
    }
    (void)n_in; (void)out_size;
}

// round 5
// speedup vs baseline: 3.2826x; 2.5630x over previous
#include <cuda_runtime.h>
#include <cuda_bf16.h>
#include <math.h>
#include <stdint.h>

// ---------------------------------------------------------------------------
// LNN — collapsed leaky-integrator MLP on tensor cores via mma.sync (bf16),
// fp32 emulated with 3-term hi/lo split: A*B ~= Ahi*Bhi + Alo*Bhi + Ahi*Blo.
// (tcgen05 PTX rejected by this build's compute_103 virtual target.)
//
//   d1    = relu(x @ W1^T + b1)            GEMM1 (epilogue: relu + bf16-split)
//   s2acc = scan(d1 @ W2^T, b2)            GEMM2 (epilogue: T-step scan + split)
//   part  = split-K s2acc @ W3^T           GEMM3 (epilogue: raw fp32 partials)
//   out   = (1-b3^T) b3 + sum_z part[z]    reduce
// ---------------------------------------------------------------------------

#define MODE_RELU 0
#define MODE_SCAN 1
#define MODE_PART 2
#define KSPLIT 2

typedef unsigned long long u64;
typedef __nv_bfloat16 bf16;

// ----- device scratch (no allocations allowed) -----
#define AL __align__(256)
__device__ AL bf16 g_xhi [1024*2048], g_xlo [1024*2048];
__device__ AL bf16 g_w1hi[4096*2048], g_w1lo[4096*2048];
__device__ AL bf16 g_w2hi[4096*4096], g_w2lo[4096*4096];
__device__ AL bf16 g_w3hi[1024*4096], g_w3lo[1024*4096];
__device__ AL bf16 g_d1hi[1024*4096], g_d1lo[1024*4096];
__device__ AL bf16 g_s2hi[1024*4096], g_s2lo[1024*4096];
__device__ AL float g_part[KSPLIT*1024*1024];

__device__ __forceinline__ float sigmoid_acc(float v) { return 1.0f / (1.0f + expf(-v)); }

__device__ __forceinline__ uint32_t smem_u32(const void* p) {
    uint32_t a;
    asm("{ .reg .u64 t; cvta.to.shared.u64 t, %1; cvt.u32.u64 %0, t; }" : "=r"(a) : "l"(p));
    return a;
}

__device__ __forceinline__ void ldsm_x4(uint32_t* r, uint32_t addr) {
    asm volatile("ldmatrix.sync.aligned.m8n8.x4.shared.b16 {%0,%1,%2,%3}, [%4];"
                 : "=r"(r[0]), "=r"(r[1]), "=r"(r[2]), "=r"(r[3]) : "r"(addr));
}

__device__ __forceinline__ void mma_bf16(float* c, const uint32_t* a, const uint32_t* b) {
    asm volatile("mma.sync.aligned.m16n8k16.row.col.f32.bf16.bf16.f32 "
                 "{%0,%1,%2,%3}, {%4,%5,%6,%7}, {%8,%9}, {%0,%1,%2,%3};"
                 : "+f"(c[0]), "+f"(c[1]), "+f"(c[2]), "+f"(c[3])
                 : "r"(a[0]), "r"(a[1]), "r"(a[2]), "r"(a[3]), "r"(b[0]), "r"(b[1]));
}

// SW64-style swizzle: row stride 64B, 16B chunk c xored by (r>>1)&3.
// Conflict-free for STS.128 and for ldmatrix 8-row phases.
__device__ __forceinline__ uint32_t sw_off(int r, int c) {
    return (uint32_t)(r * 64 + ((c ^ ((r >> 1) & 3)) << 4));
}

// ----- fp32 -> bf16 hi/lo split -----
__global__ void __launch_bounds__(256)
convert_split(const float* __restrict__ src, bf16* __restrict__ hi,
              bf16* __restrict__ lo, int n)
{
    int i = (blockIdx.x * 256 + threadIdx.x) * 4;
    if (i >= n) return;
    float4 v = *(const float4*)(src + i);
    bf16 h0 = __float2bfloat16(v.x), h1 = __float2bfloat16(v.y);
    bf16 h2 = __float2bfloat16(v.z), h3 = __float2bfloat16(v.w);
    bf16 l0 = __float2bfloat16(v.x - __bfloat162float(h0));
    bf16 l1 = __float2bfloat16(v.y - __bfloat162float(h1));
    bf16 l2 = __float2bfloat16(v.z - __bfloat162float(h2));
    bf16 l3 = __float2bfloat16(v.w - __bfloat162float(h3));
    uint2 hp, lp;
    hp.x = (uint32_t)__bfloat16_as_ushort(h0) | ((uint32_t)__bfloat16_as_ushort(h1) << 16);
    hp.y = (uint32_t)__bfloat16_as_ushort(h2) | ((uint32_t)__bfloat16_as_ushort(h3) << 16);
    lp.x = (uint32_t)__bfloat16_as_ushort(l0) | ((uint32_t)__bfloat16_as_ushort(l1) << 16);
    lp.y = (uint32_t)__bfloat16_as_ushort(l2) | ((uint32_t)__bfloat16_as_ushort(l3) << 16);
    *(uint2*)(hi + i) = hp;
    *(uint2*)(lo + i) = lp;
}

// ---------------------------------------------------------------------------
// Tensor-core GEMM:  C[M,N] = A[M,K] @ B[N,K]^T, BM=BN=128, BK=32, 8 warps.
// Warp grid 4(M) x 2(N); warp tile 32x64. mma.m16n8k16 bf16, fp32 acc.
// ---------------------------------------------------------------------------
__global__ void __launch_bounds__(256)
tc_gemm(const bf16* __restrict__ Ahi, const bf16* __restrict__ Alo,
        const bf16* __restrict__ Bhi, const bf16* __restrict__ Blo,
        const float* __restrict__ bias, float* __restrict__ Cf,
        bf16* __restrict__ OutHi, bf16* __restrict__ OutLo,
        int M, int N, int K, int lda, int mode,
        const float* __restrict__ b_taus, const int* __restrict__ Tp)
{
    __shared__ __align__(128) char smem[4 * 8192];   // Ahi, Alo, Bhi, Blo tiles
    const uint32_t sb = smem_u32(smem);
    constexpr uint32_t S_AHI = 0, S_ALO = 8192, S_BHI = 16384, S_BLO = 24576;

    const int tid = threadIdx.x;
    const int wid = tid >> 5;
    const int lid = tid & 31;
    const int warpM = wid & 3;        // 0..3 -> 32-row slice
    const int warpN = wid >> 2;       // 0..1 -> 64-col slice

    const int m0 = blockIdx.y * 128;
    const int n0 = blockIdx.x * 128;
    const int kbase = blockIdx.z * K; // split-K slab

    // global loader: thread covers 16B chunks u=tid and u=tid+256 per tile
    const int r0 = tid >> 2, c0 = tid & 3;
    const size_t step64 = (size_t)64 * lda;
    const bf16* gAh = Ahi + (size_t)(m0 + r0) * lda + kbase + c0 * 8;
    const bf16* gAl = Alo + (size_t)(m0 + r0) * lda + kbase + c0 * 8;
    const bf16* gBh = Bhi + (size_t)(n0 + r0) * lda + kbase + c0 * 8;
    const bf16* gBl = Blo + (size_t)(n0 + r0) * lda + kbase + c0 * 8;
    const uint32_t so0 = sw_off(r0, c0), so1 = sw_off(r0 + 64, c0);

    // ldmatrix per-thread addressing
    const int id = lid >> 3, rin = lid & 7;
    const int arow = warpM * 32 + (id & 1) * 8 + rin;   // + mt*16
    const int acol = (id >> 1);                         // + kk*2
    const int brow = warpN * 64 + (id >> 1) * 8 + rin;  // + nt2*16
    const int bcol = (id & 1);                          // + kk*2

    float acc[2][8][4];
#pragma unroll
    for (int mt = 0; mt < 2; mt++)
#pragma unroll
        for (int nf = 0; nf < 8; nf++)
#pragma unroll
            for (int q = 0; q < 4; q++) acc[mt][nf][q] = 0.0f;

    const int NCH = K / 32;
    uint4 pf[8];

    auto LOADCH = [&](int kc) {
        pf[0] = *(const uint4*)(gAh + kc);  pf[1] = *(const uint4*)(gAh + kc + step64);
        pf[2] = *(const uint4*)(gAl + kc);  pf[3] = *(const uint4*)(gAl + kc + step64);
        pf[4] = *(const uint4*)(gBh + kc);  pf[5] = *(const uint4*)(gBh + kc + step64);
        pf[6] = *(const uint4*)(gBl + kc);  pf[7] = *(const uint4*)(gBl + kc + step64);
    };
    auto STORECH = [&]() {
        *(uint4*)(smem + S_AHI + so0) = pf[0]; *(uint4*)(smem + S_AHI + so1) = pf[1];
        *(uint4*)(smem + S_ALO + so0) = pf[2]; *(uint4*)(smem + S_ALO + so1) = pf[3];
        *(uint4*)(smem + S_BHI + so0) = pf[4]; *(uint4*)(smem + S_BHI + so1) = pf[5];
        *(uint4*)(smem + S_BLO + so0) = pf[6]; *(uint4*)(smem + S_BLO + so1) = pf[7];
    };

    LOADCH(0);
    STORECH();
    __syncthreads();

    for (int ch = 0; ch < NCH; ch++) {
        if (ch + 1 < NCH) LOADCH((ch + 1) * 32);

#pragma unroll
        for (int kk = 0; kk < 2; kk++) {
            uint32_t ah[2][4], al[2][4];
#pragma unroll
            for (int mt = 0; mt < 2; mt++) {
                uint32_t ao = sw_off(arow + mt * 16, acol + kk * 2);
                ldsm_x4(ah[mt], sb + S_AHI + ao);
                ldsm_x4(al[mt], sb + S_ALO + ao);
            }
            uint32_t bh[4][4], bl[4][4];
#pragma unroll
            for (int nt2 = 0; nt2 < 4; nt2++) {
                uint32_t bo = sw_off(brow + nt2 * 16, bcol + kk * 2);
                ldsm_x4(bh[nt2], sb + S_BHI + bo);
                ldsm_x4(bl[nt2], sb + S_BLO + bo);
            }
#pragma unroll
            for (int mt = 0; mt < 2; mt++)
#pragma unroll
                for (int nt2 = 0; nt2 < 4; nt2++)
#pragma unroll
                    for (int h = 0; h < 2; h++) {
                        float* c = acc[mt][nt2 * 2 + h];
                        mma_bf16(c, ah[mt], &bh[nt2][h * 2]);   // hi*hi
                        mma_bf16(c, al[mt], &bh[nt2][h * 2]);   // lo*hi
                        mma_bf16(c, ah[mt], &bl[nt2][h * 2]);   // hi*lo
                    }
        }
        __syncthreads();
        if (ch + 1 < NCH) { STORECH(); __syncthreads(); }
    }

    // ---- epilogue (register fragments; no transpose) ----
    float beta1 = 0.f, beta2 = 0.f, wt0 = 0.f, invb3 = 0.f, om2 = 0.f;
    int T = 0;
    if (mode == MODE_SCAN) {
        beta1 = sigmoid_acc(b_taus[0]);
        beta2 = sigmoid_acc(b_taus[1]);
        float beta3 = sigmoid_acc(b_taus[2]);
        T     = *Tp;
        invb3 = 1.0f / beta3;
        om2   = 1.0f - beta2;
        wt0   = (1.0f - beta3) * powf(beta3, (float)(T - 1));
    }

    const int mrow = m0 + warpM * 32 + (lid >> 2);      // + mt*16 + pair*8
    const int ncol = n0 + warpN * 64 + (lid & 3) * 2;   // + nf*8

#pragma unroll
    for (int mt = 0; mt < 2; mt++) {
#pragma unroll
        for (int nf = 0; nf < 8; nf++) {
            const int col = ncol + nf * 8;
#pragma unroll
            for (int pair = 0; pair < 2; pair++) {
                const int row = mrow + mt * 16 + pair * 8;
                float v0 = acc[mt][nf][pair * 2 + 0];
                float v1 = acc[mt][nf][pair * 2 + 1];
                size_t base = (size_t)row * N + col;

                if (mode == MODE_PART) {
                    float* Cz = Cf + (size_t)blockIdx.z * M * N;
                    *(float2*)(Cz + base) = make_float2(v0, v1);
                    continue;
                }

                float bv0 = __ldg(&bias[col]), bv1 = __ldg(&bias[col + 1]);
                float o0, o1;
                if (mode == MODE_RELU) {
                    o0 = fmaxf(v0 + bv0, 0.0f);
                    o1 = fmaxf(v1 + bv1, 0.0f);
                } else { // MODE_SCAN
                    float s20 = 0.f, a0 = 0.f, s21 = 0.f, a1 = 0.f;
                    float bp = beta1, wt = wt0;
                    for (int t = 0; t < T; t++) {
                        float c1m = 1.0f - bp;
                        float d0 = fmaxf(fmaf(c1m, v0, bv0), 0.0f);
                        float d1 = fmaxf(fmaf(c1m, v1, bv1), 0.0f);
                        s20 = fmaf(beta2, s20, om2 * d0);
                        s21 = fmaf(beta2, s21, om2 * d1);
                        a0 = fmaf(wt, s20, a0);
                        a1 = fmaf(wt, s21, a1);
                        bp *= beta1;
                        wt *= invb3;
                    }
                    o0 = a0; o1 = a1;
                }
                // split to bf16 hi/lo and store packed pairs
                bf16 h0 = __float2bfloat16(o0), h1 = __float2bfloat16(o1);
                bf16 l0 = __float2bfloat16(o0 - __bfloat162float(h0));
                bf16 l1 = __float2bfloat16(o1 - __bfloat162float(h1));
                uint32_t hp = (uint32_t)__bfloat16_as_ushort(h0) |
                              ((uint32_t)__bfloat16_as_ushort(h1) << 16);
                uint32_t lp = (uint32_t)__bfloat16_as_ushort(l0) |
                              ((uint32_t)__bfloat16_as_ushort(l1) << 16);
                *(uint32_t*)(OutHi + base) = hp;
                *(uint32_t*)(OutLo + base) = lp;
            }
        }
    }
}

// out[i] = (1 - beta3^T) * b3[i % N] + sum_z part[z][i]
__global__ void __launch_bounds__(256)
reduce_out(const float* __restrict__ part, const float* __restrict__ b3,
           float* __restrict__ out, int total, int N,
           const float* __restrict__ b_taus, const int* __restrict__ Tp)
{
    int i = (blockIdx.x * blockDim.x + threadIdx.x) * 4;
    if (i >= total) return;
    float beta3  = sigmoid_acc(b_taus[2]);
    float bscale = 1.0f - powf(beta3, (float)(*Tp));
    float4 bb = *(const float4*)(b3 + (i % N));
    float4 s  = make_float4(bscale * bb.x, bscale * bb.y, bscale * bb.z, bscale * bb.w);
#pragma unroll
    for (int z = 0; z < KSPLIT; z++) {
        float4 p = *(const float4*)(part + (size_t)z * total + i);
        s.x += p.x; s.y += p.y; s.z += p.z; s.w += p.w;
    }
    *(float4*)(out + i) = s;
}

extern "C" void kernel_launch(void* const* d_in, const int* in_sizes, int n_in,
                              void* d_out, int out_size)
{
    const float* x     = (const float*)d_in[0];
    const float* W1    = (const float*)d_in[1];
    const float* b1    = (const float*)d_in[2];
    const float* W2    = (const float*)d_in[3];
    const float* b2    = (const float*)d_in[4];
    const float* W3    = (const float*)d_in[5];
    const float* b3    = (const float*)d_in[6];
    const float* btaus = (const float*)d_in[7];
    const int*   Tp    = (const int*)d_in[8];

    const int H1    = in_sizes[2];
    const int D_IN  = in_sizes[1] / H1;
    const int B     = in_sizes[0] / D_IN;
    const int H2    = in_sizes[4];
    const int D_OUT = in_sizes[6];

    bf16 *xhi, *xlo, *w1hi, *w1lo, *w2hi, *w2lo, *w3hi, *w3lo;
    bf16 *d1hi, *d1lo, *s2hi, *s2lo;
    float* part;
    cudaGetSymbolAddress((void**)&xhi,  g_xhi);  cudaGetSymbolAddress((void**)&xlo,  g_xlo);
    cudaGetSymbolAddress((void**)&w1hi, g_w1hi); cudaGetSymbolAddress((void**)&w1lo, g_w1lo);
    cudaGetSymbolAddress((void**)&w2hi, g_w2hi); cudaGetSymbolAddress((void**)&w2lo, g_w2lo);
    cudaGetSymbolAddress((void**)&w3hi, g_w3hi); cudaGetSymbolAddress((void**)&w3lo, g_w3lo);
    cudaGetSymbolAddress((void**)&d1hi, g_d1hi); cudaGetSymbolAddress((void**)&d1lo, g_d1lo);
    cudaGetSymbolAddress((void**)&s2hi, g_s2hi); cudaGetSymbolAddress((void**)&s2lo, g_s2lo);
    cudaGetSymbolAddress((void**)&part, g_part);

    float* out = (float*)d_out;

    // 0) split inputs into bf16 hi/lo
    {
        int n;
        n = B * D_IN;   convert_split<<<n / 1024, 256>>>(x,  xhi,  xlo,  n);
        n = H1 * D_IN;  convert_split<<<n / 1024, 256>>>(W1, w1hi, w1lo, n);
        n = H2 * H1;    convert_split<<<n / 1024, 256>>>(W2, w2hi, w2lo, n);
        n = D_OUT * H2; convert_split<<<n / 1024, 256>>>(W3, w3hi, w3lo, n);
    }
    // 1) d1 = relu(x @ W1^T + b1) -> bf16 hi/lo           [B, H1]
    {
        dim3 grid(H1 / 128, B / 128, 1);
        tc_gemm<<<grid, 256>>>(xhi, xlo, w1hi, w1lo, b1, nullptr, d1hi, d1lo,
                               B, H1, D_IN, D_IN, MODE_RELU, btaus, Tp);
    }
    // 2) s2acc = scan(d1 @ W2^T, b2) -> bf16 hi/lo        [B, H2]
    {
        dim3 grid(H2 / 128, B / 128, 1);
        tc_gemm<<<grid, 256>>>(d1hi, d1lo, w2hi, w2lo, b2, nullptr, s2hi, s2lo,
                               B, H2, H1, H1, MODE_SCAN, btaus, Tp);
    }
    // 3) split-K partials of s2acc @ W3^T                 [KSPLIT][B, D_OUT]
    {
        dim3 grid(D_OUT / 128, B / 128, KSPLIT);
        tc_gemm<<<grid, 256>>>(s2hi, s2lo, w3hi, w3lo, nullptr, part, nullptr, nullptr,
                               B, D_OUT, H2 / KSPLIT, H2, MODE_PART, btaus, Tp);
    }
    // 4) out = (1-b3^T) b3 + sum partials                 [B, D_OUT]
    {
        int total = B * D_OUT;
        reduce_out<<<(total / 4 + 255) / 256, 256>>>(part, b3, out, total, D_OUT, btaus, Tp);
    }
    (void)n_in; (void)out_size;
}